// round 2
// baseline (speedup 1.0000x reference)
#include <cuda_runtime.h>
#include <math.h>

// Problem constants
#define B    16
#define SQ   128
#define SK   256
#define HID  128
#define H    4
#define DK   32
#define DIM  64
#define OUT  128

// Intermediate scratch (no cudaMalloc allowed)
__device__ float g_qp[B * SQ * HID];        // projected Q  (B,SQ,HID)
__device__ float g_kp[B * SK * HID];        // projected K  (B,SK,HID)
__device__ float g_x [B * SQ * (H * DIM)]; // attention out, heads merged (B,SQ,256)

// ---------------------------------------------------------------------------
// Generic row-tiled projection: out[r,o] = dot(in[r,:in_dim], W[o,:in_dim]) + b[o]
// One block = 16 rows. W staged in smem with pitch in_dim+1 (conflict-free).
// ---------------------------------------------------------------------------
__global__ void proj_kernel(const float* __restrict__ in,
                            const float* __restrict__ W,
                            const float* __restrict__ bias,
                            float* __restrict__ out,
                            int in_dim, int out_dim) {
    extern __shared__ float sm[];
    const int TR = 16;
    const int pitch = in_dim + 1;
    float* W_s = sm;                         // out_dim * pitch
    float* x_s = sm + out_dim * pitch;       // TR * in_dim

    // stage W
    for (int idx = threadIdx.x; idx < out_dim * in_dim; idx += blockDim.x) {
        int o = idx / in_dim, i = idx - o * in_dim;
        W_s[o * pitch + i] = W[idx];
    }
    // stage input rows
    int row0 = blockIdx.x * TR;
    for (int idx = threadIdx.x; idx < TR * in_dim; idx += blockDim.x) {
        int r = idx / in_dim, i = idx - r * in_dim;
        x_s[r * in_dim + i] = in[(row0 + r) * in_dim + i];
    }
    __syncthreads();

    for (int idx = threadIdx.x; idx < TR * out_dim; idx += blockDim.x) {
        int r = idx / out_dim, o = idx - r * out_dim;
        float acc = bias[o];
        const float* w = &W_s[o * pitch];
        const float* x = &x_s[r * in_dim];
        #pragma unroll 8
        for (int i = 0; i < in_dim; i++)
            acc = fmaf(x[i], w[i], acc);
        out[(row0 + r) * out_dim + o] = acc;
    }
}

// ---------------------------------------------------------------------------
// Fused masked attention.
// Grid: B*H*(SQ/64) blocks, 256 threads.
// Phase 1: e[r,k] = exp(q·k / sqrt(DK))  -> smem (64x256)
// Phase 2: num/den contraction over k with per-channel mask, x = num/den.
// ---------------------------------------------------------------------------
__global__ void attn_kernel(const float* __restrict__ qp,
                            const float* __restrict__ kp,
                            const float* __restrict__ value,
                            const int*   __restrict__ mask,
                            float* __restrict__ xout) {
    extern __shared__ float sm[];
    float* q_s = sm;                   // 64*32
    float* k_s = q_s + 64 * 32;        // 256*33  (padded)
    float* e_s = k_s + 256 * 33;       // 64*256

    const int blk = blockIdx.x;
    const int qt  = blk & 1;           // q-tile (SQ/64 = 2)
    const int h   = (blk >> 1) & 3;
    const int b   = blk >> 3;
    const int q0  = qt * 64;

    // stage Q tile: heads are channel slices [h*32, h*32+32)
    for (int idx = threadIdx.x; idx < 64 * 32; idx += 256) {
        int r = idx >> 5, i = idx & 31;
        q_s[idx] = qp[(b * SQ + q0 + r) * HID + h * DK + i];
    }
    // stage K tile (padded pitch 33)
    for (int idx = threadIdx.x; idx < 256 * 32; idx += 256) {
        int kk = idx >> 5, i = idx & 31;
        k_s[kk * 33 + i] = kp[(b * SK + kk) * HID + h * DK + i];
    }
    __syncthreads();

    // Phase 1: one thread per k column
    {
        const int kk = threadIdx.x;          // 0..255
        float kreg[32];
        #pragma unroll
        for (int i = 0; i < 32; i++) kreg[i] = k_s[kk * 33 + i];
        const float scale = 0.17677669529663687f;   // 1/sqrt(32)
        for (int r = 0; r < 64; r++) {
            float acc = 0.f;
            #pragma unroll
            for (int i = 0; i < 32; i++)
                acc = fmaf(q_s[r * 32 + i], kreg[i], acc);
            e_s[r * 256 + kk] = __expf(acc * scale);
        }
    }
    __syncthreads();

    // Phase 2: thread -> (d = tid%64, group g = tid/64 handling 16 q-rows)
    const int d = threadIdx.x & 63;
    const int g = threadIdx.x >> 6;      // 0..3
    float num[16], den[16];
    #pragma unroll
    for (int j = 0; j < 16; j++) { num[j] = 0.f; den[j] = 0.f; }
    float vsum = 0.f;

    for (int kk = 0; kk < 256; kk++) {
        int gi = (b * SK + kk) * DIM + d;
        float v = value[gi];
        int   m = mask[gi];
        vsum += v;
        float mv = m ? v : 0.f;
        float mm = m ? 1.f : 0.f;
        #pragma unroll
        for (int j = 0; j < 16; j++) {
            float ee = e_s[(g * 16 + j) * 256 + kk];
            num[j] = fmaf(ee, mv, num[j]);
            den[j] = fmaf(ee, mm, den[j]);
        }
    }

    #pragma unroll
    for (int j = 0; j < 16; j++) {
        int r = g * 16 + j;
        float res = (den[j] > 0.f) ? (num[j] / den[j]) : (vsum * (1.0f / 256.0f));
        // merged-heads layout: x[b, q, h*DIM + d]
        xout[(b * SQ + q0 + r) * (H * DIM) + h * DIM + d] = res;
    }
}

// ---------------------------------------------------------------------------
extern "C" void kernel_launch(void* const* d_in, const int* in_sizes, int n_in,
                              void* d_out, int out_size) {
    const float* query = (const float*)d_in[0];
    const float* key   = (const float*)d_in[1];
    const float* value = (const float*)d_in[2];
    const int*   mask  = (const int*)  d_in[3];
    const float* Wq    = (const float*)d_in[4];
    const float* bq    = (const float*)d_in[5];
    const float* Wk    = (const float*)d_in[6];
    const float* bk    = (const float*)d_in[7];
    const float* Wo    = (const float*)d_in[8];
    const float* bo    = (const float*)d_in[9];
    float* out = (float*)d_out;

    float* qp; cudaGetSymbolAddress((void**)&qp, g_qp);
    float* kp; cudaGetSymbolAddress((void**)&kp, g_kp);
    float* xb; cudaGetSymbolAddress((void**)&xb, g_x);

    // dynamic smem sizes
    const int smem_proj_128 = (HID * (HID + 1) + 16 * HID) * (int)sizeof(float);       // ~74 KB
    const int smem_proj_out = (OUT * (H * DIM + 1) + 16 * (H * DIM)) * (int)sizeof(float); // ~148 KB
    const int smem_attn     = (64 * 32 + 256 * 33 + 64 * 256) * (int)sizeof(float);    // ~107 KB

    cudaFuncSetAttribute(proj_kernel, cudaFuncAttributeMaxDynamicSharedMemorySize, smem_proj_out);
    cudaFuncSetAttribute(attn_kernel, cudaFuncAttributeMaxDynamicSharedMemorySize, smem_attn);

    // Q projection: rows = B*SQ = 2048
    proj_kernel<<<(B * SQ) / 16, 256, smem_proj_128>>>(query, Wq, bq, qp, HID, HID);
    // K projection: rows = B*SK = 4096
    proj_kernel<<<(B * SK) / 16, 256, smem_proj_128>>>(key, Wk, bk, kp, HID, HID);
    // fused attention: B*H*(SQ/64) = 128 blocks
    attn_kernel<<<B * H * (SQ / 64), 256, smem_attn>>>(qp, kp, value, mask, xb);
    // output projection: rows = B*SQ, in 256 -> out 128
    proj_kernel<<<(B * SQ) / 16, 256, smem_proj_out>>>(xb, Wo, bo, out, H * DIM, OUT);
}

// round 3
// speedup vs baseline: 1.9198x; 1.9198x over previous
#include <cuda_runtime.h>
#include <math.h>

// Problem constants
#define B    16
#define SQ   128
#define SK   256
#define HID  128
#define H    4
#define DK   32
#define DIM  64
#define OUT  128

// GEMM tiling
#define BM 64
#define BN 32
#define BK 16
#define PA 68   // As pitch (floats): 68*4=272 bytes, 16B-aligned rows
#define PB 36   // Bs pitch (floats): 36*4=144 bytes, 8B-aligned rows

// Intermediate scratch (no cudaMalloc allowed)
__device__ float g_qp[B * SQ * HID];        // projected Q  (B,SQ,HID)
__device__ float g_kp[B * SK * HID];        // projected K  (B,SK,HID)
__device__ float g_x [B * SQ * (H * DIM)];  // attention out, heads merged (B,SQ,256)

// ---------------------------------------------------------------------------
// Register-blocked GEMM tile: C[M,128] = A[M,KDIM] @ W[128,KDIM]^T + bias
// Block computes a 64x32 tile; thread computes 4x2. N is fixed at 128 (4 n-tiles).
// tile index: mt = tile>>2, nt = tile&3.
// ---------------------------------------------------------------------------
template<int KDIM>
__device__ __forceinline__ void gemm_body(const float* __restrict__ A,
                                          const float* __restrict__ W,
                                          const float* __restrict__ bias,
                                          float* __restrict__ C,
                                          int tile, float* As, float* Bs) {
    const int t  = threadIdx.x;
    const int ty = t >> 4;          // 0..15 -> rows ty*4..ty*4+3
    const int tx = t & 15;          // 0..15 -> cols tx*2..tx*2+1
    const int row0 = (tile >> 2) * BM;
    const int col0 = (tile & 3) * BN;

    const float b0 = bias[col0 + tx * 2 + 0];
    const float b1 = bias[col0 + tx * 2 + 1];

    float acc[4][2];
    #pragma unroll
    for (int i = 0; i < 4; i++) { acc[i][0] = 0.f; acc[i][1] = 0.f; }

    const int lm  = t >> 2;         // 0..63 (A row within tile)
    const int lk4 = (t & 3) * 4;    // 0,4,8,12 (k offset, float4)
    const int ln  = (t & 127) >> 2; // 0..31 (W row within tile, threads <128)

    for (int kt = 0; kt < KDIM / BK; kt++) {
        // Stage A (64x16), transposed to As[k][m]
        float4 av = *(const float4*)(A + (row0 + lm) * KDIM + kt * BK + lk4);
        As[(lk4 + 0) * PA + lm] = av.x;
        As[(lk4 + 1) * PA + lm] = av.y;
        As[(lk4 + 2) * PA + lm] = av.z;
        As[(lk4 + 3) * PA + lm] = av.w;
        // Stage W tile (32x16), transposed to Bs[k][n]
        if (t < 128) {
            float4 wv = *(const float4*)(W + (col0 + ln) * KDIM + kt * BK + lk4);
            Bs[(lk4 + 0) * PB + ln] = wv.x;
            Bs[(lk4 + 1) * PB + ln] = wv.y;
            Bs[(lk4 + 2) * PB + ln] = wv.z;
            Bs[(lk4 + 3) * PB + ln] = wv.w;
        }
        __syncthreads();

        #pragma unroll
        for (int kk = 0; kk < BK; kk++) {
            float4 a = *(const float4*)(As + kk * PA + ty * 4);
            float2 b = *(const float2*)(Bs + kk * PB + tx * 2);
            acc[0][0] = fmaf(a.x, b.x, acc[0][0]);
            acc[0][1] = fmaf(a.x, b.y, acc[0][1]);
            acc[1][0] = fmaf(a.y, b.x, acc[1][0]);
            acc[1][1] = fmaf(a.y, b.y, acc[1][1]);
            acc[2][0] = fmaf(a.z, b.x, acc[2][0]);
            acc[2][1] = fmaf(a.z, b.y, acc[2][1]);
            acc[3][0] = fmaf(a.w, b.x, acc[3][0]);
            acc[3][1] = fmaf(a.w, b.y, acc[3][1]);
        }
        __syncthreads();
    }

    #pragma unroll
    for (int i = 0; i < 4; i++) {
        float2 o;
        o.x = acc[i][0] + b0;
        o.y = acc[i][1] + b1;
        *(float2*)(C + (row0 + ty * 4 + i) * 128 + col0 + tx * 2) = o;
    }
}

// Combined Q and K projection (fills the chip in one launch: 128 + 256 blocks)
__global__ __launch_bounds__(256) void qk_proj_kernel(
        const float* __restrict__ q,  const float* __restrict__ Wq,
        const float* __restrict__ bq, float* __restrict__ qp,
        const float* __restrict__ k,  const float* __restrict__ Wk,
        const float* __restrict__ bk, float* __restrict__ kp) {
    __shared__ float As[BK * PA];
    __shared__ float Bs[BK * PB];
    if (blockIdx.x < 128)
        gemm_body<128>(q, Wq, bq, qp, blockIdx.x, As, Bs);
    else
        gemm_body<128>(k, Wk, bk, kp, blockIdx.x - 128, As, Bs);
}

__global__ __launch_bounds__(256) void o_proj_kernel(
        const float* __restrict__ x,  const float* __restrict__ Wo,
        const float* __restrict__ bo, float* __restrict__ out) {
    __shared__ float As[BK * PA];
    __shared__ float Bs[BK * PB];
    gemm_body<256>(x, Wo, bo, out, blockIdx.x, As, Bs);
}

// ---------------------------------------------------------------------------
// Fused masked attention.
// Grid: B*H*(SQ/32) = 256 blocks, 256 threads. q-tile = 32 -> 70.6KB smem,
// 2 blocks/SM.
// Phase 1: e[r,k] = exp(q·k / sqrt(DK))  -> smem (32x256)
// Phase 2: num/den contraction over k with per-channel mask, x = num/den.
// ---------------------------------------------------------------------------
#define QT 32
__global__ __launch_bounds__(256) void attn_kernel(
        const float* __restrict__ qp,
        const float* __restrict__ kp,
        const float* __restrict__ value,
        const int*   __restrict__ mask,
        float* __restrict__ xout) {
    extern __shared__ float sm[];
    float* q_s = sm;                    // QT*32
    float* k_s = q_s + QT * 32;         // 256*33 (padded)
    float* e_s = k_s + 256 * 33;        // QT*256

    const int blk = blockIdx.x;
    const int qt  = blk & 3;            // 4 q-tiles of 32
    const int h   = (blk >> 2) & 3;
    const int b   = blk >> 4;
    const int q0  = qt * QT;

    // stage Q tile: head h is channel slice [h*32, h*32+32)
    for (int idx = threadIdx.x; idx < QT * 32; idx += 256) {
        int r = idx >> 5, i = idx & 31;
        q_s[idx] = qp[(b * SQ + q0 + r) * HID + h * DK + i];
    }
    // stage K tile (padded pitch 33)
    for (int idx = threadIdx.x; idx < 256 * 32; idx += 256) {
        int kk = idx >> 5, i = idx & 31;
        k_s[kk * 33 + i] = kp[(b * SK + kk) * HID + h * DK + i];
    }
    __syncthreads();

    // Phase 1: one thread per k column
    {
        const int kk = threadIdx.x;     // 0..255
        float kreg[32];
        #pragma unroll
        for (int i = 0; i < 32; i++) kreg[i] = k_s[kk * 33 + i];
        const float scale = 0.17677669529663687f;   // 1/sqrt(32)
        #pragma unroll 4
        for (int r = 0; r < QT; r++) {
            float acc = 0.f;
            #pragma unroll
            for (int i = 0; i < 32; i++)
                acc = fmaf(q_s[r * 32 + i], kreg[i], acc);
            e_s[r * 256 + kk] = __expf(acc * scale);
        }
    }
    __syncthreads();

    // Phase 2: thread -> (d = tid%64, group g = tid/64 handling 8 q-rows)
    const int d = threadIdx.x & 63;
    const int g = threadIdx.x >> 6;     // 0..3
    float num[8], den[8];
    #pragma unroll
    for (int j = 0; j < 8; j++) { num[j] = 0.f; den[j] = 0.f; }
    float vsum = 0.f;

    for (int kk = 0; kk < 256; kk++) {
        int gi = (b * SK + kk) * DIM + d;
        float v = value[gi];
        int   m = mask[gi];
        vsum += v;
        float mv = m ? v : 0.f;
        float mm = m ? 1.f : 0.f;
        #pragma unroll
        for (int j = 0; j < 8; j++) {
            float ee = e_s[(g * 8 + j) * 256 + kk];   // warp-broadcast
            num[j] = fmaf(ee, mv, num[j]);
            den[j] = fmaf(ee, mm, den[j]);
        }
    }

    #pragma unroll
    for (int j = 0; j < 8; j++) {
        int r = g * 8 + j;
        float res = (den[j] > 0.f) ? (num[j] / den[j]) : (vsum * (1.0f / 256.0f));
        // merged-heads layout: x[b, q, h*DIM + d]
        xout[(b * SQ + q0 + r) * (H * DIM) + h * DIM + d] = res;
    }
}

// ---------------------------------------------------------------------------
extern "C" void kernel_launch(void* const* d_in, const int* in_sizes, int n_in,
                              void* d_out, int out_size) {
    const float* query = (const float*)d_in[0];
    const float* key   = (const float*)d_in[1];
    const float* value = (const float*)d_in[2];
    const int*   mask  = (const int*)  d_in[3];
    const float* Wq    = (const float*)d_in[4];
    const float* bq    = (const float*)d_in[5];
    const float* Wk    = (const float*)d_in[6];
    const float* bk    = (const float*)d_in[7];
    const float* Wo    = (const float*)d_in[8];
    const float* bo    = (const float*)d_in[9];
    float* out = (float*)d_out;

    float* qp; cudaGetSymbolAddress((void**)&qp, g_qp);
    float* kp; cudaGetSymbolAddress((void**)&kp, g_kp);
    float* xb; cudaGetSymbolAddress((void**)&xb, g_x);

    const int smem_attn = (QT * 32 + 256 * 33 + QT * 256) * (int)sizeof(float); // ~70.6KB
    cudaFuncSetAttribute(attn_kernel, cudaFuncAttributeMaxDynamicSharedMemorySize, smem_attn);

    // Q projection (2048x128x128) + K projection (4096x128x128), one launch
    qk_proj_kernel<<<128 + 256, 256>>>(query, Wq, bq, qp, key, Wk, bk, kp);
    // fused attention: B*H*(SQ/32) = 256 blocks
    attn_kernel<<<B * H * (SQ / QT), 256, smem_attn>>>(qp, kp, value, mask, xb);
    // output projection: 2048x128x256
    o_proj_kernel<<<128, 256>>>(xb, Wo, bo, out);
}

// round 4
// speedup vs baseline: 3.1650x; 1.6486x over previous
#include <cuda_runtime.h>
#include <math.h>

// Problem constants
#define B    16
#define SQ   128
#define SK   256
#define HID  128
#define H    4
#define DK   32
#define DIM  64
#define OUT  128

// Intermediate scratch (no cudaMalloc allowed)
__device__ float g_qp[B * SQ * HID];        // projected Q  (B,SQ,HID)
__device__ float g_kp[B * SK * HID];        // projected K  (B,SK,HID)
__device__ float g_x [B * SQ * (H * DIM)];  // attention out, heads merged (B,SQ,256)

// ---------------------------------------------------------------------------
// Register-blocked GEMM: C[M,128] = A[M,KDIM] @ W[128,KDIM]^T + bias
// Block tile 32x64, 128 threads, 4x4 per thread (16 FMA : 2 LDS.128).
// tile: mt = tile>>1 (row block), nt = tile&1 (col block of 64).
// ---------------------------------------------------------------------------
template<int KDIM>
__device__ __forceinline__ void gemm_body(const float* __restrict__ A,
                                          const float* __restrict__ W,
                                          const float* __restrict__ bias,
                                          float* __restrict__ C,
                                          int tile, float* As, float* Bs) {
    const int t  = threadIdx.x;      // 0..127
    const int ty = t >> 4;           // 0..7  -> rows ty*4..+3
    const int tx = t & 15;           // 0..15 -> cols tx*4..+3
    const int row0 = (tile >> 1) * 32;
    const int col0 = (tile & 1) * 64;

    const float4 bias4 = *(const float4*)(bias + col0 + tx * 4);

    float acc[4][4];
    #pragma unroll
    for (int i = 0; i < 4; i++)
        #pragma unroll
        for (int j = 0; j < 4; j++) acc[i][j] = 0.f;

    const int lmA = t >> 2;          // 0..31
    const int lkA = (t & 3) * 4;     // 0,4,8,12
    const int lnB = t >> 1;          // 0..63
    const int lkB = (t & 1) * 8;     // 0,8

    for (int kt = 0; kt < KDIM / 16; kt++) {
        // Stage A (32 rows x 16 k), transposed -> As[k][m], pitch 32
        float4 av = *(const float4*)(A + (row0 + lmA) * KDIM + kt * 16 + lkA);
        As[(lkA + 0) * 32 + lmA] = av.x;
        As[(lkA + 1) * 32 + lmA] = av.y;
        As[(lkA + 2) * 32 + lmA] = av.z;
        As[(lkA + 3) * 32 + lmA] = av.w;
        // Stage W tile (64 n-rows x 16 k), transposed -> Bs[k][n], pitch 64
        float4 b0 = *(const float4*)(W + (col0 + lnB) * KDIM + kt * 16 + lkB);
        float4 b1 = *(const float4*)(W + (col0 + lnB) * KDIM + kt * 16 + lkB + 4);
        Bs[(lkB + 0) * 64 + lnB] = b0.x;
        Bs[(lkB + 1) * 64 + lnB] = b0.y;
        Bs[(lkB + 2) * 64 + lnB] = b0.z;
        Bs[(lkB + 3) * 64 + lnB] = b0.w;
        Bs[(lkB + 4) * 64 + lnB] = b1.x;
        Bs[(lkB + 5) * 64 + lnB] = b1.y;
        Bs[(lkB + 6) * 64 + lnB] = b1.z;
        Bs[(lkB + 7) * 64 + lnB] = b1.w;
        __syncthreads();

        #pragma unroll
        for (int kk = 0; kk < 16; kk++) {
            float4 a = *(const float4*)(As + kk * 32 + ty * 4);
            float4 b = *(const float4*)(Bs + kk * 64 + tx * 4);
            acc[0][0] = fmaf(a.x, b.x, acc[0][0]);
            acc[0][1] = fmaf(a.x, b.y, acc[0][1]);
            acc[0][2] = fmaf(a.x, b.z, acc[0][2]);
            acc[0][3] = fmaf(a.x, b.w, acc[0][3]);
            acc[1][0] = fmaf(a.y, b.x, acc[1][0]);
            acc[1][1] = fmaf(a.y, b.y, acc[1][1]);
            acc[1][2] = fmaf(a.y, b.z, acc[1][2]);
            acc[1][3] = fmaf(a.y, b.w, acc[1][3]);
            acc[2][0] = fmaf(a.z, b.x, acc[2][0]);
            acc[2][1] = fmaf(a.z, b.y, acc[2][1]);
            acc[2][2] = fmaf(a.z, b.z, acc[2][2]);
            acc[2][3] = fmaf(a.z, b.w, acc[2][3]);
            acc[3][0] = fmaf(a.w, b.x, acc[3][0]);
            acc[3][1] = fmaf(a.w, b.y, acc[3][1]);
            acc[3][2] = fmaf(a.w, b.z, acc[3][2]);
            acc[3][3] = fmaf(a.w, b.w, acc[3][3]);
        }
        __syncthreads();
    }

    #pragma unroll
    for (int i = 0; i < 4; i++) {
        float4 o;
        o.x = acc[i][0] + bias4.x;
        o.y = acc[i][1] + bias4.y;
        o.z = acc[i][2] + bias4.z;
        o.w = acc[i][3] + bias4.w;
        *(float4*)(C + (row0 + ty * 4 + i) * 128 + col0 + tx * 4) = o;
    }
}

// Q-proj (2048 rows) + K-proj (4096 rows) in one launch: 128 + 256 = 384 blocks
__global__ __launch_bounds__(128) void qk_proj_kernel(
        const float* __restrict__ q,  const float* __restrict__ Wq,
        const float* __restrict__ bq, float* __restrict__ qp,
        const float* __restrict__ k,  const float* __restrict__ Wk,
        const float* __restrict__ bk, float* __restrict__ kp) {
    __shared__ float As[16 * 32];
    __shared__ float Bs[16 * 64];
    if (blockIdx.x < 128)
        gemm_body<128>(q, Wq, bq, qp, blockIdx.x, As, Bs);
    else
        gemm_body<128>(k, Wk, bk, kp, blockIdx.x - 128, As, Bs);
}

__global__ __launch_bounds__(128) void o_proj_kernel(
        const float* __restrict__ x,  const float* __restrict__ Wo,
        const float* __restrict__ bo, float* __restrict__ out) {
    __shared__ float As[16 * 32];
    __shared__ float Bs[16 * 64];
    gemm_body<256>(x, Wo, bo, out, blockIdx.x, As, Bs);
}

// ---------------------------------------------------------------------------
// Fused masked attention. Grid: B*H*(SQ/32) = 256 blocks, 256 threads.
// Phase 1: e[k][q] = exp(q·k / sqrt(DK)) -> smem, k-major, pitch 36
// Phase 2: smem-GEMM over k: (num|den)[q][d] = e @ (mask*value | mask),
//          vm staged in 64-k chunks (reuses K-tile buffer), thread = 4q x 2d.
// ---------------------------------------------------------------------------
#define QT 32
#define EPITCH 36
__global__ __launch_bounds__(256) void attn_kernel(
        const float* __restrict__ qp,
        const float* __restrict__ kp,
        const float* __restrict__ value,
        const int*   __restrict__ mask,
        float* __restrict__ xout) {
    extern __shared__ float sm[];
    float* q_s = sm;                         // 32*32          = 1024
    float* e_t = q_s + QT * 32;              // 256*36 k-major = 9216
    float* buf = e_t + SK * EPITCH;          // max(256*33, 64*128) = 8448
    float4* vm4 = (float4*)buf;              // phase-2 view: [64][32] float4

    const int blk = blockIdx.x;
    const int qt  = blk & 3;                 // 4 q-tiles of 32
    const int h   = (blk >> 2) & 3;
    const int b   = blk >> 4;
    const int q0  = qt * QT;
    const int tid = threadIdx.x;

    // stage Q tile (head slice [h*32, h*32+32))
    for (int idx = tid; idx < QT * 32; idx += 256) {
        int r = idx >> 5, i = idx & 31;
        q_s[idx] = qp[(b * SQ + q0 + r) * HID + h * DK + i];
    }
    // stage K tile, pitch 33 (conflict-free column reads)
    for (int idx = tid; idx < SK * 32; idx += 256) {
        int kk = idx >> 5, i = idx & 31;
        buf[kk * 33 + i] = kp[(b * SK + kk) * HID + h * DK + i];
    }
    __syncthreads();

    // Phase 1: one thread per k column; e_t[k][q]
    {
        const int kk = tid;                  // 0..255
        float kreg[32];
        #pragma unroll
        for (int i = 0; i < 32; i++) kreg[i] = buf[kk * 33 + i];
        const float scale = 0.17677669529663687f;   // 1/sqrt(32)
        #pragma unroll 4
        for (int r = 0; r < QT; r++) {
            float acc = 0.f;
            #pragma unroll
            for (int i = 0; i < 32; i++)
                acc = fmaf(q_s[r * 32 + i], kreg[i], acc);
            e_t[kk * EPITCH + r] = __expf(acc * scale);
        }
    }

    // Phase 2: thread = (qy = tid>>5 in 0..7 -> 4 q rows, dx = tid&31 -> d pair)
    const int qy = tid >> 5;
    const int dx = tid & 31;
    float num[4][2], den[4][2];
    #pragma unroll
    for (int i = 0; i < 4; i++) {
        num[i][0] = 0.f; num[i][1] = 0.f;
        den[i][0] = 0.f; den[i][1] = 0.f;
    }

    for (int c = 0; c < 4; c++) {
        __syncthreads();                     // prev chunk consumed / phase-1 k reads done
        // stage vm chunk: 64 k-rows, float4 = (mv0, m0, mv1, m1) per d-pair
        #pragma unroll
        for (int it = 0; it < 8; it++) {
            int item = tid + it * 256;       // 0..2047
            int lk = item >> 5, d2 = item & 31;
            int gbase = (b * SK + c * 64 + lk) * DIM + d2 * 2;
            float2 v = *(const float2*)(value + gbase);
            int2  mm = *(const int2*)(mask + gbase);
            float4 w;
            w.x = mm.x ? v.x : 0.f;  w.y = mm.x ? 1.f : 0.f;
            w.z = mm.y ? v.y : 0.f;  w.w = mm.y ? 1.f : 0.f;
            vm4[lk * 32 + d2] = w;
        }
        __syncthreads();

        #pragma unroll 8
        for (int kk = 0; kk < 64; kk++) {
            float4 ev = *(const float4*)(e_t + (c * 64 + kk) * EPITCH + qy * 4);  // broadcast
            float4 w  = vm4[kk * 32 + dx];
            num[0][0] = fmaf(ev.x, w.x, num[0][0]);
            den[0][0] = fmaf(ev.x, w.y, den[0][0]);
            num[0][1] = fmaf(ev.x, w.z, num[0][1]);
            den[0][1] = fmaf(ev.x, w.w, den[0][1]);
            num[1][0] = fmaf(ev.y, w.x, num[1][0]);
            den[1][0] = fmaf(ev.y, w.y, den[1][0]);
            num[1][1] = fmaf(ev.y, w.z, num[1][1]);
            den[1][1] = fmaf(ev.y, w.w, den[1][1]);
            num[2][0] = fmaf(ev.z, w.x, num[2][0]);
            den[2][0] = fmaf(ev.z, w.y, den[2][0]);
            num[2][1] = fmaf(ev.z, w.z, num[2][1]);
            den[2][1] = fmaf(ev.z, w.w, den[2][1]);
            num[3][0] = fmaf(ev.w, w.x, num[3][0]);
            den[3][0] = fmaf(ev.w, w.y, den[3][0]);
            num[3][1] = fmaf(ev.w, w.z, num[3][1]);
            den[3][1] = fmaf(ev.w, w.w, den[3][1]);
        }
    }

    // Fallback for all-masked channel (prob ~2^-256, but keep exact semantics):
    // softmax over all-NEG column is uniform -> mean(value) over k.
    bool bad = false;
    #pragma unroll
    for (int i = 0; i < 4; i++)
        if (den[i][0] == 0.f || den[i][1] == 0.f) bad = true;
    float vs0 = 0.f, vs1 = 0.f;
    if (bad) {
        for (int kk = 0; kk < SK; kk++) {
            float2 v = *(const float2*)(value + (b * SK + kk) * DIM + dx * 2);
            vs0 += v.x; vs1 += v.y;
        }
        vs0 *= (1.0f / 256.0f); vs1 *= (1.0f / 256.0f);
    }

    #pragma unroll
    for (int i = 0; i < 4; i++) {
        int r = qy * 4 + i;
        float2 o;
        o.x = (den[i][0] > 0.f) ? (num[i][0] / den[i][0]) : vs0;
        o.y = (den[i][1] > 0.f) ? (num[i][1] / den[i][1]) : vs1;
        // merged-heads layout: x[b, q, h*DIM + d]
        *(float2*)(xout + (b * SQ + q0 + r) * (H * DIM) + h * DIM + dx * 2) = o;
    }
}

// ---------------------------------------------------------------------------
extern "C" void kernel_launch(void* const* d_in, const int* in_sizes, int n_in,
                              void* d_out, int out_size) {
    const float* query = (const float*)d_in[0];
    const float* key   = (const float*)d_in[1];
    const float* value = (const float*)d_in[2];
    const int*   mask  = (const int*)  d_in[3];
    const float* Wq    = (const float*)d_in[4];
    const float* bq    = (const float*)d_in[5];
    const float* Wk    = (const float*)d_in[6];
    const float* bk    = (const float*)d_in[7];
    const float* Wo    = (const float*)d_in[8];
    const float* bo    = (const float*)d_in[9];
    float* out = (float*)d_out;

    float* qp; cudaGetSymbolAddress((void**)&qp, g_qp);
    float* kp; cudaGetSymbolAddress((void**)&kp, g_kp);
    float* xb; cudaGetSymbolAddress((void**)&xb, g_x);

    const int smem_attn = (QT * 32 + SK * EPITCH + SK * 33) * (int)sizeof(float); // ~74.8KB
    cudaFuncSetAttribute(attn_kernel, cudaFuncAttributeMaxDynamicSharedMemorySize, smem_attn);

    // Q projection (2048x128x128) + K projection (4096x128x128)
    qk_proj_kernel<<<384, 128>>>(query, Wq, bq, qp, key, Wk, bk, kp);
    // fused attention: 256 blocks
    attn_kernel<<<B * H * (SQ / QT), 256, smem_attn>>>(qp, kp, value, mask, xb);
    // output projection: 2048x128x256
    o_proj_kernel<<<128, 128>>>(xb, Wo, bo, out);
}